// round 16
// baseline (speedup 1.0000x reference)
#include <cuda_runtime.h>
#include <cuda_bf16.h>
#include <math.h>
#include <stdint.h>

#define CC 96
#define DD 40
#define HH 48
#define WW_ 40
#define BB 2
#define WIN_D 5
#define WIN_H 6
#define WIN_W 5
#define NT 150
#define NWD 8
#define NWH 8
#define NWW 8
#define NWIN 1024
#define SPD (DD*HH*WW_)   /* 76800 */
#define TOT (BB*SPD)      /* 153600 */
#define HID 384

// ---------------- scratch (device globals; no allocation) ----------------
__device__ __align__(128) float          g_xt [TOT*CC];
__device__ __align__(128) __nv_bfloat16  g_q  [NWIN*NT*CC];
__device__ __align__(128) __nv_bfloat16  g_k  [NWIN*NT*CC];
__device__ __align__(128) __nv_bfloat16  g_v  [NWIN*NT*CC];
__device__ __align__(128) float          g_x2 [TOT*CC];
__device__ __align__(128) float          g_x3 [TOT*CC];
__device__ __align__(128) float          g_bias[NT*NT];
__device__ __align__(128) __nv_bfloat16  g_wqT[96*96];
__device__ __align__(128) __nv_bfloat16  g_wkT[96*96];
__device__ __align__(128) __nv_bfloat16  g_wvT[96*96];
__device__ __align__(128) __nv_bfloat16  g_wpT[96*96];
__device__ __align__(128) __nv_bfloat16  g_w1T[HID*96];
__device__ __align__(128) __nv_bfloat16  g_w2T[96*HID];

__device__ __forceinline__ float warp_sum(float v) {
    #pragma unroll
    for (int o = 16; o > 0; o >>= 1) v += __shfl_xor_sync(0xffffffffu, v, o);
    return v;
}
__device__ __forceinline__ float gelu_fast(float x) {
    float z = 0.79788456080286535588f * (x + 0.044715f * x * x * x);
    float t = __expf(2.0f * z);
    return x * t / (t + 1.0f);
}
__device__ __forceinline__ uint32_t pack_bf16(float lo, float hi) {
    uint32_t r;
    asm("cvt.rn.bf16x2.f32 %0, %1, %2;" : "=r"(r) : "f"(hi), "f"(lo));
    return r;
}
__device__ __forceinline__ void mma16816(float c[4],
                                         uint32_t a0, uint32_t a1, uint32_t a2, uint32_t a3,
                                         uint32_t b0, uint32_t b1) {
    asm volatile(
        "mma.sync.aligned.m16n8k16.row.col.f32.bf16.bf16.f32 "
        "{%0,%1,%2,%3}, {%4,%5,%6,%7}, {%8,%9}, {%0,%1,%2,%3};"
        : "+f"(c[0]), "+f"(c[1]), "+f"(c[2]), "+f"(c[3])
        : "r"(a0), "r"(a1), "r"(a2), "r"(a3), "r"(b0), "r"(b1));
}
__device__ __forceinline__ uint32_t smem_u32(const void* p) {
    uint32_t a;
    asm("{ .reg .u64 t; cvta.to.shared.u64 t, %1; cvt.u32.u64 %0, t; }" : "=r"(a) : "l"(p));
    return a;
}
__device__ __forceinline__ void cp16(uint32_t dst, const void* src) {
    asm volatile("cp.async.cg.shared.global [%0], [%1], 16;" :: "r"(dst), "l"(src));
}
#define CP_COMMIT() asm volatile("cp.async.commit_group;")
#define CP_WAIT0()  asm volatile("cp.async.wait_group 0;")

// ---------------- K0a: relative position bias table ----------------
__global__ void bias_kernel(const float* __restrict__ rel_bias) {
    int i = blockIdx.x * blockDim.x + threadIdx.x;
    if (i >= NT * NT) return;
    int n = i / NT, m = i % NT;
    int nd = n / 30, nh = (n / 5) % 6, nw = n % 5;
    int md = m / 30, mh = (m / 5) % 6, mw = m % 5;
    int idx = (nd - md + 4) * 99 + (nh - mh + 5) * 9 + (nw - mw + 4);
    g_bias[i] = rel_bias[idx];
}

// ---------------- K0b: pre-convert weights to transposed bf16 ----------------
__global__ void prep_w_kernel(const float* __restrict__ wq, const float* __restrict__ wkv,
                              const float* __restrict__ wproj,
                              const float* __restrict__ w1, const float* __restrict__ w2) {
    int i = blockIdx.x * 256 + threadIdx.x;
    if (i < 9216) {
        int n = i / 96, k = i % 96;
        g_wqT[i] = __float2bfloat16_rn(wq[k * 96 + n]);
        g_wpT[i] = __float2bfloat16_rn(wproj[k * 96 + n]);
        g_wkT[i] = __float2bfloat16_rn(wkv[k * 192 + n]);
        g_wvT[i] = __float2bfloat16_rn(wkv[k * 192 + 96 + n]);
    }
    if (i < 36864) {
        int n = i / 96, k = i % 96;
        g_w1T[i] = __float2bfloat16_rn(w1[(long)k * HID + n]);
        int n2 = i / 384, k2 = i % 384;
        g_w2T[i] = __float2bfloat16_rn(w2[(long)k2 * 96 + n2]);
    }
}

// ---------------- K1/K2: transpose + LN + projection via mma.sync ----------------
#define LTS 129
#define ASTR2 102
#define WSTR 104
#define LA_OFF 49536
#define LN_SMEM 75648
template<int COUT, bool ISQ>
__global__ void __launch_bounds__(256, 3)
lnproj_mma_kernel(const float* __restrict__ in,
                  const float* __restrict__ gamma,
                  const float* __restrict__ beta,
                  const float* __restrict__ bvec) {
    extern __shared__ __align__(16) char smem[];
    float* tile = (float*)smem;
    __nv_bfloat16* sWT = (__nv_bfloat16*)smem;
    __nv_bfloat16* sA  = (__nv_bfloat16*)(smem + LA_OFF);

    int tid = threadIdx.x, wid = tid >> 5, lane = tid & 31;
    int g = lane >> 2, tig = lane & 3;
    long t0 = (long)blockIdx.x * 128;
    int b  = (int)(t0 / SPD);
    int s0 = (int)(t0 % SPD);
    int r0 = wid * 16;
    uint32_t sb = smem_u32(smem);

    float gm0 = gamma[lane], gm1 = gamma[lane + 32], gm2 = gamma[lane + 64];
    float bt0 = beta[lane],  bt1 = beta[lane + 32],  bt2 = beta[lane + 64];

    const float* inb = in + (long)b * 96 * SPD + s0;
    for (int i = tid; i < 96 * 32; i += 256) {
        int c = i >> 5, t4 = (i & 31) << 2;
        float4 v = *(const float4*)(inb + (long)c * SPD + t4);
        float* tp = tile + c * LTS + t4;
        tp[0] = v.x; tp[1] = v.y; tp[2] = v.z; tp[3] = v.w;
    }
    __syncthreads();

    if (ISQ) {
        for (int i = tid; i < 24 * 128; i += 256) {
            int t = i / 24, c4 = (i % 24) << 2;
            float4 v;
            v.x = tile[(c4 + 0) * LTS + t];
            v.y = tile[(c4 + 1) * LTS + t];
            v.z = tile[(c4 + 2) * LTS + t];
            v.w = tile[(c4 + 3) * LTS + t];
            *(float4*)(g_xt + (t0 + t) * 96 + c4) = v;
        }
    }

    #pragma unroll 1
    for (int it = 0; it < 16; it++) {
        int t = r0 + it;
        float v0 = tile[lane * LTS + t];
        float v1 = tile[(lane + 32) * LTS + t];
        float v2 = tile[(lane + 64) * LTS + t];
        float mean = warp_sum(v0 + v1 + v2) * (1.0f / 96.0f);
        float var  = warp_sum(v0 * v0 + v1 * v1 + v2 * v2) * (1.0f / 96.0f) - mean * mean;
        float inv  = rsqrtf(var + 1e-5f);
        sA[t * ASTR2 + lane]      = __float2bfloat16_rn((v0 - mean) * inv * gm0 + bt0);
        sA[t * ASTR2 + lane + 32] = __float2bfloat16_rn((v1 - mean) * inv * gm1 + bt1);
        sA[t * ASTR2 + lane + 64] = __float2bfloat16_rn((v2 - mean) * inv * gm2 + bt2);
    }

    long base0, base1;
    {
        long bases[2];
        int rows[2] = { r0 + g, r0 + g + 8 };
        #pragma unroll
        for (int rr = 0; rr < 2; rr++) {
            long t = t0 + rows[rr];
            int s = (int)(t % SPD);
            int d = s / (HH * WW_), h = (s / WW_) % HH, w = s % WW_;
            int wi = ((b * NWD + d / WIN_D) * NWH + h / WIN_H) * NWW + w / WIN_W;
            int n  = (d % WIN_D) * 30 + (h % WIN_H) * 5 + (w % WIN_W);
            bases[rr] = ((long)wi * NT + n) * 96;
        }
        base0 = bases[0]; base1 = bases[1];
    }

    const int NHALF = COUT / 96;
    #pragma unroll
    for (int half = 0; half < NHALF; half++) {
        __syncthreads();
        const __nv_bfloat16* wsrc = ISQ ? g_wqT : (half == 0 ? g_wkT : g_wvT);
        for (int i = tid; i < 96 * 12; i += 256) {
            int n = i / 12, c = i % 12;
            cp16(sb + n * (WSTR * 2) + c * 16, (const char*)(wsrc + n * 96) + c * 16);
        }
        CP_COMMIT(); CP_WAIT0();
        __syncthreads();

        float c[12][4];
        #pragma unroll
        for (int nt = 0; nt < 12; nt++) { c[nt][0]=0.f; c[nt][1]=0.f; c[nt][2]=0.f; c[nt][3]=0.f; }
        #pragma unroll
        for (int kk = 0; kk < 6; kk++) {
            int kb = kk * 16 + tig * 2;
            uint32_t a0 = *(const uint32_t*)(sA + (r0 + g)     * ASTR2 + kb);
            uint32_t a1 = *(const uint32_t*)(sA + (r0 + g + 8) * ASTR2 + kb);
            uint32_t a2 = *(const uint32_t*)(sA + (r0 + g)     * ASTR2 + kb + 8);
            uint32_t a3 = *(const uint32_t*)(sA + (r0 + g + 8) * ASTR2 + kb + 8);
            #pragma unroll
            for (int nt = 0; nt < 12; nt++) {
                int n = nt * 8 + g;
                uint32_t b0 = *(const uint32_t*)(sWT + n * WSTR + kb);
                uint32_t b1 = *(const uint32_t*)(sWT + n * WSTR + kb + 8);
                mma16816(c[nt], a0, a1, a2, a3, b0, b1);
            }
        }
        __nv_bfloat16* dst = ISQ ? g_q : (half == 0 ? g_k : g_v);
        #pragma unroll
        for (int nt = 0; nt < 12; nt++) {
            int col = nt * 8 + tig * 2;
            float b0v = __ldg(bvec + half * 96 + col);
            float b1v = __ldg(bvec + half * 96 + col + 1);
            *(uint32_t*)(dst + base0 + col) = pack_bf16(c[nt][0] + b0v, c[nt][1] + b1v);
            *(uint32_t*)(dst + base1 + col) = pack_bf16(c[nt][2] + b0v, c[nt][3] + b1v);
        }
    }
}

// ---------------- K3: attention, 2 CTAs per window (80 rows each) ----------------
#define AQS 104
#define ASQ_OFF 0
#define ASK_OFF 16640
#define ASV_OFF 48256
#define ASW_OFF 81536
#define ASBP_OFF 101504
#define ATT_SMEM 101888

__global__ void __launch_bounds__(160, 2)
attn_mma_kernel(const float* __restrict__ bproj) {
    extern __shared__ __align__(16) char smem[];
    __nv_bfloat16* sQ  = (__nv_bfloat16*)(smem + ASQ_OFF);
    __nv_bfloat16* sK  = (__nv_bfloat16*)(smem + ASK_OFF);
    __nv_bfloat16* sV  = (__nv_bfloat16*)(smem + ASV_OFF);
    __nv_bfloat16* sWp = (__nv_bfloat16*)(smem + ASW_OFF);
    float* sBp = (float*)(smem + ASBP_OFF);

    int tid = threadIdx.x, wid = tid >> 5, lane = tid & 31;
    int g = lane >> 2, tig = lane & 3;
    int wi   = blockIdx.x >> 1;
    int half = blockIdx.x & 1;
    int r0 = wid * 16;
    int rowoff = half * 80;
    const float scale = 0.102062072615965696f;

    const char* gq = (const char*)(g_q + (long)wi * NT * 96);
    const char* gk = (const char*)(g_k + (long)wi * NT * 96);
    const char* gv = (const char*)(g_v + (long)wi * NT * 96);

    uint32_t sb = smem_u32(smem);
    int qrows = half ? 70 : 80;
    for (int i = tid; i < qrows * 12; i += 160) {
        int r = i / 12, c = i % 12;
        cp16(sb + ASQ_OFF + r * 208 + c * 16, gq + (rowoff + r) * 192 + c * 16);
    }
    for (int i = tid; i < 150 * 12; i += 160) {
        int r = i / 12, c = i % 12;
        cp16(sb + ASK_OFF + r * 208 + c * 16, gk + r * 192 + c * 16);
        cp16(sb + ASV_OFF + r * 208 + c * 16, gv + r * 192 + c * 16);
    }
    for (int i = tid; i < 96 * 12; i += 160) {
        int n = i / 12, c = i % 12;
        cp16(sb + ASW_OFF + n * 208 + c * 16, (const char*)(g_wpT + n * 96) + c * 16);
    }
    if (tid < 96) sBp[tid] = bproj[tid];
    {
        uint32_t* zk = (uint32_t*)(sK + 150 * AQS);
        uint32_t* zv = (uint32_t*)(sV + 150 * AQS);
        for (int i = tid; i < 520; i += 160) zv[i] = 0u;
        for (int i = tid; i < 104; i += 160) zk[i] = 0u;
        if (half) {
            uint32_t* zq = (uint32_t*)(sQ + 70 * AQS);
            for (int i = tid; i < 520; i += 160) zq[i] = 0u;
        }
    }
    CP_COMMIT(); CP_WAIT0();
    __syncthreads();

    float cs[19][4];
    #pragma unroll
    for (int nt = 0; nt < 19; nt++) { cs[nt][0]=0.f; cs[nt][1]=0.f; cs[nt][2]=0.f; cs[nt][3]=0.f; }
    #pragma unroll
    for (int kk = 0; kk < 6; kk++) {
        int kb = kk * 16 + tig * 2;
        uint32_t a0 = *(const uint32_t*)(sQ + (r0 + g)     * AQS + kb);
        uint32_t a1 = *(const uint32_t*)(sQ + (r0 + g + 8) * AQS + kb);
        uint32_t a2 = *(const uint32_t*)(sQ + (r0 + g)     * AQS + kb + 8);
        uint32_t a3 = *(const uint32_t*)(sQ + (r0 + g + 8) * AQS + kb + 8);
        #pragma unroll
        for (int nt = 0; nt < 19; nt++) {
            int m = nt * 8 + g;
            uint32_t b0 = *(const uint32_t*)(sK + m * AQS + kb);
            uint32_t b1 = *(const uint32_t*)(sK + m * AQS + kb + 8);
            mma16816(cs[nt], a0, a1, a2, a3, b0, b1);
        }
    }

    int n0r = rowoff + r0 + g, n1r = rowoff + r0 + g + 8;
    float mx0 = -1e30f, mx1 = -1e30f;
    #pragma unroll
    for (int nt = 0; nt < 19; nt++) {
        int m = nt * 8 + tig * 2;
        if (m < NT) {
            if (n0r < NT) {
                float2 bv = *(const float2*)(g_bias + n0r * NT + m);
                cs[nt][0] = cs[nt][0] * scale + bv.x;
                cs[nt][1] = cs[nt][1] * scale + bv.y;
            } else { cs[nt][0] = 0.f; cs[nt][1] = 0.f; }
            if (n1r < NT) {
                float2 bv = *(const float2*)(g_bias + n1r * NT + m);
                cs[nt][2] = cs[nt][2] * scale + bv.x;
                cs[nt][3] = cs[nt][3] * scale + bv.y;
            } else { cs[nt][2] = 0.f; cs[nt][3] = 0.f; }
            mx0 = fmaxf(mx0, fmaxf(cs[nt][0], cs[nt][1]));
            mx1 = fmaxf(mx1, fmaxf(cs[nt][2], cs[nt][3]));
        } else {
            cs[nt][0] = -1e30f; cs[nt][1] = -1e30f;
            cs[nt][2] = -1e30f; cs[nt][3] = -1e30f;
        }
    }
    mx0 = fmaxf(mx0, __shfl_xor_sync(0xffffffffu, mx0, 1));
    mx0 = fmaxf(mx0, __shfl_xor_sync(0xffffffffu, mx0, 2));
    mx1 = fmaxf(mx1, __shfl_xor_sync(0xffffffffu, mx1, 1));
    mx1 = fmaxf(mx1, __shfl_xor_sync(0xffffffffu, mx1, 2));
    float s0 = 0.f, s1 = 0.f;
    #pragma unroll
    for (int nt = 0; nt < 19; nt++) {
        cs[nt][0] = __expf(cs[nt][0] - mx0);
        cs[nt][1] = __expf(cs[nt][1] - mx0);
        cs[nt][2] = __expf(cs[nt][2] - mx1);
        cs[nt][3] = __expf(cs[nt][3] - mx1);
        s0 += cs[nt][0] + cs[nt][1];
        s1 += cs[nt][2] + cs[nt][3];
    }
    s0 += __shfl_xor_sync(0xffffffffu, s0, 1);
    s0 += __shfl_xor_sync(0xffffffffu, s0, 2);
    s1 += __shfl_xor_sync(0xffffffffu, s1, 1);
    s1 += __shfl_xor_sync(0xffffffffu, s1, 2);
    float inv0 = 1.0f / s0, inv1 = 1.0f / s1;

    uint32_t pa[10][4];
    #pragma unroll
    for (int kt = 0; kt < 10; kt++) {
        int e = 2 * kt, o = 2 * kt + 1;
        pa[kt][0] = pack_bf16(cs[e][0] * inv0, cs[e][1] * inv0);
        pa[kt][1] = pack_bf16(cs[e][2] * inv1, cs[e][3] * inv1);
        if (o < 19) {
            pa[kt][2] = pack_bf16(cs[o][0] * inv0, cs[o][1] * inv0);
            pa[kt][3] = pack_bf16(cs[o][2] * inv1, cs[o][3] * inv1);
        } else { pa[kt][2] = 0u; pa[kt][3] = 0u; }
    }

    float co[12][4];
    #pragma unroll
    for (int nt = 0; nt < 12; nt++) { co[nt][0]=0.f; co[nt][1]=0.f; co[nt][2]=0.f; co[nt][3]=0.f; }
    #pragma unroll
    for (int kt = 0; kt < 10; kt++) {
        int kb = kt * 16 + tig * 2;
        const uint16_t* v0p = (const uint16_t*)(sV + (kb + 0) * AQS);
        const uint16_t* v1p = (const uint16_t*)(sV + (kb + 1) * AQS);
        const uint16_t* v8p = (const uint16_t*)(sV + (kb + 8) * AQS);
        const uint16_t* v9p = (const uint16_t*)(sV + (kb + 9) * AQS);
        #pragma unroll
        for (int nt = 0; nt < 12; nt++) {
            int n = nt * 8 + g;
            uint32_t b0 = (uint32_t)v0p[n] | ((uint32_t)v1p[n] << 16);
            uint32_t b1 = (uint32_t)v8p[n] | ((uint32_t)v9p[n] << 16);
            mma16816(co[nt], pa[kt][0], pa[kt][1], pa[kt][2], pa[kt][3], b0, b1);
        }
    }

    uint32_t oa[6][4];
    #pragma unroll
    for (int kt = 0; kt < 6; kt++) {
        oa[kt][0] = pack_bf16(co[2*kt][0],   co[2*kt][1]);
        oa[kt][1] = pack_bf16(co[2*kt][2],   co[2*kt][3]);
        oa[kt][2] = pack_bf16(co[2*kt+1][0], co[2*kt+1][1]);
        oa[kt][3] = pack_bf16(co[2*kt+1][2], co[2*kt+1][3]);
    }
    float c2r[12][4];
    #pragma unroll
    for (int nt = 0; nt < 12; nt++) { c2r[nt][0]=0.f; c2r[nt][1]=0.f; c2r[nt][2]=0.f; c2r[nt][3]=0.f; }
    #pragma unroll
    for (int kt = 0; kt < 6; kt++) {
        int kb = kt * 16 + tig * 2;
        #pragma unroll
        for (int nt = 0; nt < 12; nt++) {
            int cp = nt * 8 + g;
            uint32_t b0 = *(const uint32_t*)(sWp + cp * AQS + kb);
            uint32_t b1 = *(const uint32_t*)(sWp + cp * AQS + kb + 8);
            mma16816(c2r[nt], oa[kt][0], oa[kt][1], oa[kt][2], oa[kt][3], b0, b1);
        }
    }

    int iww = wi & 7, iwh = (wi >> 3) & 7, iwd = (wi >> 6) & 7, b = wi >> 9;
    long t0r = -1, t1r = -1;
    if (n0r < NT) {
        int zd = n0r / 30, zh = (n0r / 5) % 6, zw = n0r % 5;
        int d = iwd * WIN_D + zd, h = iwh * WIN_H + zh, w = iww * WIN_W + zw;
        t0r = (long)b * SPD + ((long)d * HH + h) * WW_ + w;
    }
    if (n1r < NT) {
        int zd = n1r / 30, zh = (n1r / 5) % 6, zw = n1r % 5;
        int d = iwd * WIN_D + zd, h = iwh * WIN_H + zh, w = iww * WIN_W + zw;
        t1r = (long)b * SPD + ((long)d * HH + h) * WW_ + w;
    }
    #pragma unroll
    for (int nt = 0; nt < 12; nt++) {
        int cp = nt * 8 + tig * 2;
        float b0v = sBp[cp], b1v = sBp[cp + 1];
        if (t0r >= 0) {
            float2 x = *(const float2*)(g_xt + t0r * 96 + cp);
            float2 o = make_float2(x.x + c2r[nt][0] + b0v, x.y + c2r[nt][1] + b1v);
            *(float2*)(g_x2 + t0r * 96 + cp) = o;
        }
        if (t1r >= 0) {
            float2 x = *(const float2*)(g_xt + t1r * 96 + cp);
            float2 o = make_float2(x.x + c2r[nt][2] + b0v, x.y + c2r[nt][3] + b1v);
            *(float2*)(g_x2 + t1r * 96 + cp) = o;
        }
    }
}

// ---------------- K4: fused LN2 + MLP via mma.sync (3 CTAs/SM) ----------------
// smem 75,648B: sA stride 100, W1 stride 98 (uint32-staged), W2 stride 130.
// GEMM2 interleaved after each GEMM1 half -> h shrinks to 8 fragments.
#define MASTR 100
#define MW1S  98
#define MW2S  130
#define MA_OFF    0       /* 128*200 = 25600 */
#define MW1_OFF   25600   /* 128*196 = 25088 */
#define MW2_OFF   50688   /* 96*260  = 24960 */
#define MLP_SMEM  75648

__global__ void __launch_bounds__(256, 3)
mlp_mma_kernel(const float* __restrict__ g2, const float* __restrict__ b2ln,
               const float* __restrict__ b1, const float* __restrict__ b2) {
    extern __shared__ __align__(16) char smem[];
    __nv_bfloat16* sA   = (__nv_bfloat16*)(smem + MA_OFF);
    __nv_bfloat16* sW1T = (__nv_bfloat16*)(smem + MW1_OFF);
    __nv_bfloat16* sW2T = (__nv_bfloat16*)(smem + MW2_OFF);
    uint32_t* sW1w = (uint32_t*)(smem + MW1_OFF);
    uint32_t* sW2w = (uint32_t*)(smem + MW2_OFF);

    int tid = threadIdx.x, wid = tid >> 5, lane = tid & 31;
    int g = lane >> 2, tig = lane & 3;
    long t0 = (long)blockIdx.x * 128;
    int r0 = wid * 16;

    // LN params in registers
    float gm0 = g2[lane], gm1 = g2[lane + 32], gm2 = g2[lane + 64];
    float bt0 = b2ln[lane], bt1 = b2ln[lane + 32], bt2 = b2ln[lane + 64];

    #pragma unroll 1
    for (int it = 0; it < 16; it++) {
        int r = r0 + it;
        const float* xr = g_x2 + (t0 + r) * 96;
        float v0 = xr[lane], v1 = xr[lane + 32], v2 = xr[lane + 64];
        float mean = warp_sum(v0 + v1 + v2) * (1.0f / 96.0f);
        float var  = warp_sum(v0 * v0 + v1 * v1 + v2 * v2) * (1.0f / 96.0f) - mean * mean;
        float inv  = rsqrtf(var + 1e-5f);
        sA[r * MASTR + lane]      = __float2bfloat16_rn((v0 - mean) * inv * gm0 + bt0);
        sA[r * MASTR + lane + 32] = __float2bfloat16_rn((v1 - mean) * inv * gm1 + bt1);
        sA[r * MASTR + lane + 64] = __float2bfloat16_rn((v2 - mean) * inv * gm2 + bt2);
    }

    float c2[12][4];
    #pragma unroll
    for (int nt = 0; nt < 12; nt++) { c2[nt][0]=0.f; c2[nt][1]=0.f; c2[nt][2]=0.f; c2[nt][3]=0.f; }

    const uint32_t* w1p = (const uint32_t*)g_w1T;
    const uint32_t* w2p = (const uint32_t*)g_w2T;

    for (int j = 0; j < 3; j++) {
        __syncthreads();   // prior-chunk W reads done
        // stage W1 chunk: 128 rows x 48 words, smem stride 49 words
        for (int i = tid; i < 128 * 48; i += 256) {
            int n = i / 48, w = i - n * 48;
            sW1w[n * 49 + w] = w1p[(long)(j * 128 + n) * 48 + w];
        }
        // stage W2 chunk: 96 rows x 64 words, smem stride 65 words
        for (int i = tid; i < 96 * 64; i += 256) {
            int n = i >> 6, w = i & 63;
            sW2w[n * 65 + w] = w2p[(long)n * 192 + j * 64 + w];
        }
        __syncthreads();

        #pragma unroll
        for (int half = 0; half < 2; half++) {
            float c1[8][4];
            #pragma unroll
            for (int nt = 0; nt < 8; nt++) { c1[nt][0]=0.f; c1[nt][1]=0.f; c1[nt][2]=0.f; c1[nt][3]=0.f; }
            #pragma unroll
            for (int kk = 0; kk < 6; kk++) {
                int kb = kk * 16 + tig * 2;
                uint32_t a0 = *(const uint32_t*)(sA + (r0 + g) * MASTR + kb);
                uint32_t a1 = *(const uint32_t*)(sA + (r0 + g + 8) * MASTR + kb);
                uint32_t a2 = *(const uint32_t*)(sA + (r0 + g) * MASTR + kb + 8);
                uint32_t a3 = *(const uint32_t*)(sA + (r0 + g + 8) * MASTR + kb + 8);
                #pragma unroll
                for (int nt = 0; nt < 8; nt++) {
                    int n = (half * 8 + nt) * 8 + g;
                    uint32_t b0 = *(const uint32_t*)(sW1T + n * MW1S + kb);
                    uint32_t b1v = *(const uint32_t*)(sW1T + n * MW1S + kb + 8);
                    mma16816(c1[nt], a0, a1, a2, a3, b0, b1v);
                }
            }
            // gelu + bias -> 8 h fragments (registers)
            uint32_t h8[8][2];
            #pragma unroll
            for (int nt = 0; nt < 8; nt++) {
                int nn = (half * 8 + nt) * 8 + tig * 2;
                float bb0 = __ldg(b1 + j * 128 + nn);
                float bb1 = __ldg(b1 + j * 128 + nn + 1);
                h8[nt][0] = pack_bf16(gelu_fast(c1[nt][0] + bb0), gelu_fast(c1[nt][1] + bb1));
                h8[nt][1] = pack_bf16(gelu_fast(c1[nt][2] + bb0), gelu_fast(c1[nt][3] + bb1));
            }
            // GEMM2 partial: kk = half*4 .. half*4+3
            #pragma unroll
            for (int l = 0; l < 4; l++) {
                int kk = half * 4 + l;
                uint32_t a0 = h8[2 * l][0],     a1 = h8[2 * l][1];
                uint32_t a2 = h8[2 * l + 1][0], a3 = h8[2 * l + 1][1];
                int kb = kk * 16 + tig * 2;
                #pragma unroll
                for (int nt = 0; nt < 12; nt++) {
                    int n = nt * 8 + g;
                    uint32_t b0 = *(const uint32_t*)(sW2T + n * MW2S + kb);
                    uint32_t b1v = *(const uint32_t*)(sW2T + n * MW2S + kb + 8);
                    mma16816(c2[nt], a0, a1, a2, a3, b0, b1v);
                }
            }
        }
    }

    #pragma unroll
    for (int nt = 0; nt < 12; nt++) {
        int n = nt * 8 + tig * 2;
        long ra = t0 + r0 + g;
        float bb0 = __ldg(b2 + n), bb1 = __ldg(b2 + n + 1);
        float2 x0 = *(const float2*)(g_x2 + ra * 96 + n);
        float2 x1 = *(const float2*)(g_x2 + (ra + 8) * 96 + n);
        float2 o0 = make_float2(x0.x + c2[nt][0] + bb0, x0.y + c2[nt][1] + bb1);
        float2 o1 = make_float2(x1.x + c2[nt][2] + bb0, x1.y + c2[nt][3] + bb1);
        *(float2*)(g_x3 + ra * 96 + n) = o0;
        *(float2*)(g_x3 + (ra + 8) * 96 + n) = o1;
    }
}

// ---------------- K6: conv3d 3x3x3, 96 -> 3 — row-tiled, 2 w-voxels/thread ----------------
__global__ void __launch_bounds__(160, 4)
conv_kernel(const float* __restrict__ cw, const float* __restrict__ cbias,
            float* __restrict__ out) {
    __shared__ __align__(16) float sWc[27 * 3 * 96];
    __shared__ __align__(16) float sRow[42 * 100];
    __shared__ float sCB[3];
    int tid = threadIdx.x;
    for (int i = tid; i < 27 * 3 * 96; i += 160) {
        int k = i / 288, r = i % 288, o = r / 96, c = r % 96;
        sWc[i] = cw[((long)o * 96 + c) * 27 + k];
    }
    if (tid < 3) sCB[tid] = cbias[tid];

    int bid = blockIdx.x;
    int hg = bid % 6, d = (bid / 6) % DD, b = bid / (6 * DD);
    int h0 = hg * 8;
    int h_local = tid / 20, wl = tid % 20;
    int h = h0 + h_local;

    float acc[2][3];
    #pragma unroll
    for (int v = 0; v < 2; v++) { acc[v][0] = 0.f; acc[v][1] = 0.f; acc[v][2] = 0.f; }

    for (int d2 = d - 1; d2 <= d + 1; d2++) {
        if ((unsigned)d2 >= DD) continue;
        int kd = d2 - d;
        for (int h2 = h0 - 1; h2 <= h0 + 8; h2++) {
            if ((unsigned)h2 >= HH) continue;
            __syncthreads();
            const float4* src = (const float4*)(g_x3 +
                ((long)b * SPD + (long)d2 * HH * WW_ + (long)h2 * WW_) * 96);
            for (int i = tid; i < 960; i += 160) {
                int w2 = i / 24, c4 = i % 24;
                *(float4*)(sRow + (w2 + 1) * 100 + c4 * 4) = src[i];
            }
            if (tid < 48) {
                int v = tid / 24, c4 = tid % 24;
                int w2p = v ? 41 : 0;
                *(float4*)(sRow + w2p * 100 + c4 * 4) = make_float4(0.f, 0.f, 0.f, 0.f);
            }
            __syncthreads();
            int kh = h2 - h;
            if (kh < -1 || kh > 1) continue;
            #pragma unroll
            for (int kw = -1; kw <= 1; kw++) {
                int k = (kd + 1) * 9 + (kh + 1) * 3 + (kw + 1);
                const float4* wk  = (const float4*)(sWc + k * 288);
                const float4* xr0 = (const float4*)(sRow + (wl + kw + 1) * 100);
                const float4* xr1 = (const float4*)(sRow + (wl + 20 + kw + 1) * 100);
                float a00 = 0.f, a01 = 0.f, a02 = 0.f;
                float a10 = 0.f, a11 = 0.f, a12 = 0.f;
                #pragma unroll 8
                for (int c4 = 0; c4 < 24; c4++) {
                    float4 x0 = xr0[c4];
                    float4 x1 = xr1[c4];
                    float4 w0 = wk[c4];
                    float4 w1 = wk[24 + c4];
                    float4 w2v = wk[48 + c4];
                    a00 += x0.x * w0.x + x0.y * w0.y + x0.z * w0.z + x0.w * w0.w;
                    a01 += x0.x * w1.x + x0.y * w1.y + x0.z * w1.z + x0.w * w1.w;
                    a02 += x0.x * w2v.x + x0.y * w2v.y + x0.z * w2v.z + x0.w * w2v.w;
                    a10 += x1.x * w0.x + x1.y * w0.y + x1.z * w0.z + x1.w * w0.w;
                    a11 += x1.x * w1.x + x1.y * w1.y + x1.z * w1.z + x1.w * w1.w;
                    a12 += x1.x * w2v.x + x1.y * w2v.y + x1.z * w2v.z + x1.w * w2v.w;
                }
                acc[0][0] += a00; acc[0][1] += a01; acc[0][2] += a02;
                acc[1][0] += a10; acc[1][1] += a11; acc[1][2] += a12;
            }
        }
    }
    #pragma unroll
    for (int v = 0; v < 2; v++) {
        long sp = (long)d * HH * WW_ + (long)h * WW_ + (wl + 20 * v);
        #pragma unroll
        for (int o = 0; o < 3; o++)
            out[((long)b * 3 + o) * SPD + sp] = acc[v][o] + sCB[o];
    }
}

// ---------------- launch (stream fork/join for the independent front) ----------------
extern "C" void kernel_launch(void* const* d_in, const int* in_sizes, int n_in,
                              void* d_out, int out_size) {
    const float* I_m    = (const float*)d_in[0];
    const float* I_f    = (const float*)d_in[1];
    const float* ln1q_g = (const float*)d_in[2];
    const float* ln1q_b = (const float*)d_in[3];
    const float* ln1kv_g= (const float*)d_in[4];
    const float* ln1kv_b= (const float*)d_in[5];
    const float* wq     = (const float*)d_in[6];
    const float* bq     = (const float*)d_in[7];
    const float* wkv    = (const float*)d_in[8];
    const float* bkv    = (const float*)d_in[9];
    const float* wproj  = (const float*)d_in[10];
    const float* bproj  = (const float*)d_in[11];
    const float* relb   = (const float*)d_in[12];
    const float* ln2_g  = (const float*)d_in[13];
    const float* ln2_b  = (const float*)d_in[14];
    const float* w1     = (const float*)d_in[15];
    const float* b1     = (const float*)d_in[16];
    const float* w2     = (const float*)d_in[17];
    const float* b2     = (const float*)d_in[18];
    const float* cw     = (const float*)d_in[19];
    const float* cb     = (const float*)d_in[20];
    float* out = (float*)d_out;

    static cudaStream_t s1, s2, s3;
    static cudaEvent_t efork, ej1, ej2, ej3;
    static bool inited = false;
    if (!inited) {
        cudaStreamCreateWithFlags(&s1, cudaStreamNonBlocking);
        cudaStreamCreateWithFlags(&s2, cudaStreamNonBlocking);
        cudaStreamCreateWithFlags(&s3, cudaStreamNonBlocking);
        cudaEventCreateWithFlags(&efork, cudaEventDisableTiming);
        cudaEventCreateWithFlags(&ej1, cudaEventDisableTiming);
        cudaEventCreateWithFlags(&ej2, cudaEventDisableTiming);
        cudaEventCreateWithFlags(&ej3, cudaEventDisableTiming);
        inited = true;
    }

    cudaFuncSetAttribute(lnproj_mma_kernel<96,  true >, cudaFuncAttributeMaxDynamicSharedMemorySize, LN_SMEM);
    cudaFuncSetAttribute(lnproj_mma_kernel<192, false>, cudaFuncAttributeMaxDynamicSharedMemorySize, LN_SMEM);
    cudaFuncSetAttribute(attn_mma_kernel, cudaFuncAttributeMaxDynamicSharedMemorySize, ATT_SMEM);
    cudaFuncSetAttribute(mlp_mma_kernel, cudaFuncAttributeMaxDynamicSharedMemorySize, MLP_SMEM);

    cudaStream_t s0 = 0;

    cudaEventRecord(efork, s0);
    cudaStreamWaitEvent(s1, efork, 0);
    cudaStreamWaitEvent(s2, efork, 0);
    cudaStreamWaitEvent(s3, efork, 0);

    bias_kernel<<<(NT*NT + 255) / 256, 256, 0, s1>>>(relb);
    prep_w_kernel<<<144, 256, 0, s1>>>(wq, wkv, wproj, w1, w2);
    lnproj_mma_kernel<96,  true ><<<TOT / 128, 256, LN_SMEM, s2>>>(I_m, ln1q_g,  ln1q_b,  bq);
    lnproj_mma_kernel<192, false><<<TOT / 128, 256, LN_SMEM, s3>>>(I_f, ln1kv_g, ln1kv_b, bkv);

    cudaEventRecord(ej1, s1);
    cudaEventRecord(ej2, s2);
    cudaEventRecord(ej3, s3);
    cudaStreamWaitEvent(s0, ej1, 0);
    cudaStreamWaitEvent(s0, ej2, 0);
    cudaStreamWaitEvent(s0, ej3, 0);

    attn_mma_kernel<<<NWIN * 2, 160, ATT_SMEM, s0>>>(bproj);
    mlp_mma_kernel<<<TOT / 128, 256, MLP_SMEM, s0>>>(ln2_g, ln2_b, b1, b2);
    conv_kernel<<<BB * DD * 6, 160, 0, s0>>>(cw, cb, out);
}

// round 17
// speedup vs baseline: 1.1766x; 1.1766x over previous
#include <cuda_runtime.h>
#include <cuda_bf16.h>
#include <math.h>
#include <stdint.h>

#define CC 96
#define DD 40
#define HH 48
#define WW_ 40
#define BB 2
#define WIN_D 5
#define WIN_H 6
#define WIN_W 5
#define NT 150
#define NWD 8
#define NWH 8
#define NWW 8
#define NWIN 1024
#define SPD (DD*HH*WW_)   /* 76800 */
#define TOT (BB*SPD)      /* 153600 */
#define HID 384

// ---------------- scratch (device globals; no allocation) ----------------
__device__ __align__(128) float          g_xt [TOT*CC];
__device__ __align__(128) __nv_bfloat16  g_q  [NWIN*NT*CC];
__device__ __align__(128) __nv_bfloat16  g_k  [NWIN*NT*CC];
__device__ __align__(128) __nv_bfloat16  g_v  [NWIN*NT*CC];
__device__ __align__(128) float          g_x2 [TOT*CC];
__device__ __align__(128) float          g_x3 [TOT*CC];
__device__ __align__(128) float          g_bias[NT*NT];
__device__ __align__(128) __nv_bfloat16  g_wqT[96*96];
__device__ __align__(128) __nv_bfloat16  g_wkT[96*96];
__device__ __align__(128) __nv_bfloat16  g_wvT[96*96];
__device__ __align__(128) __nv_bfloat16  g_wpT[96*96];
__device__ __align__(128) __nv_bfloat16  g_w1T[HID*96];
__device__ __align__(128) __nv_bfloat16  g_w2T[96*HID];

__device__ __forceinline__ float warp_sum(float v) {
    #pragma unroll
    for (int o = 16; o > 0; o >>= 1) v += __shfl_xor_sync(0xffffffffu, v, o);
    return v;
}
__device__ __forceinline__ float gelu_fast(float x) {
    float z = 0.79788456080286535588f * (x + 0.044715f * x * x * x);
    float t = __expf(2.0f * z);
    return x * t / (t + 1.0f);
}
__device__ __forceinline__ uint32_t pack_bf16(float lo, float hi) {
    uint32_t r;
    asm("cvt.rn.bf16x2.f32 %0, %1, %2;" : "=r"(r) : "f"(hi), "f"(lo));
    return r;
}
__device__ __forceinline__ void mma16816(float c[4],
                                         uint32_t a0, uint32_t a1, uint32_t a2, uint32_t a3,
                                         uint32_t b0, uint32_t b1) {
    asm volatile(
        "mma.sync.aligned.m16n8k16.row.col.f32.bf16.bf16.f32 "
        "{%0,%1,%2,%3}, {%4,%5,%6,%7}, {%8,%9}, {%0,%1,%2,%3};"
        : "+f"(c[0]), "+f"(c[1]), "+f"(c[2]), "+f"(c[3])
        : "r"(a0), "r"(a1), "r"(a2), "r"(a3), "r"(b0), "r"(b1));
}
__device__ __forceinline__ uint32_t smem_u32(const void* p) {
    uint32_t a;
    asm("{ .reg .u64 t; cvta.to.shared.u64 t, %1; cvt.u32.u64 %0, t; }" : "=r"(a) : "l"(p));
    return a;
}
__device__ __forceinline__ void cp16(uint32_t dst, const void* src) {
    asm volatile("cp.async.cg.shared.global [%0], [%1], 16;" :: "r"(dst), "l"(src));
}
#define CP_COMMIT() asm volatile("cp.async.commit_group;")
#define CP_WAIT0()  asm volatile("cp.async.wait_group 0;")

// ---------------- K0a: relative position bias table ----------------
__global__ void bias_kernel(const float* __restrict__ rel_bias) {
    int i = blockIdx.x * blockDim.x + threadIdx.x;
    if (i >= NT * NT) return;
    int n = i / NT, m = i % NT;
    int nd = n / 30, nh = (n / 5) % 6, nw = n % 5;
    int md = m / 30, mh = (m / 5) % 6, mw = m % 5;
    int idx = (nd - md + 4) * 99 + (nh - mh + 5) * 9 + (nw - mw + 4);
    g_bias[i] = rel_bias[idx];
}

// ---------------- K0b: pre-convert weights to transposed bf16 ----------------
__global__ void prep_w_kernel(const float* __restrict__ wq, const float* __restrict__ wkv,
                              const float* __restrict__ wproj,
                              const float* __restrict__ w1, const float* __restrict__ w2) {
    int i = blockIdx.x * 256 + threadIdx.x;
    if (i < 9216) {
        int n = i / 96, k = i % 96;
        g_wqT[i] = __float2bfloat16_rn(wq[k * 96 + n]);
        g_wpT[i] = __float2bfloat16_rn(wproj[k * 96 + n]);
        g_wkT[i] = __float2bfloat16_rn(wkv[k * 192 + n]);
        g_wvT[i] = __float2bfloat16_rn(wkv[k * 192 + 96 + n]);
    }
    if (i < 36864) {
        int n = i / 96, k = i % 96;
        g_w1T[i] = __float2bfloat16_rn(w1[(long)k * HID + n]);
        int n2 = i / 384, k2 = i % 384;
        g_w2T[i] = __float2bfloat16_rn(w2[(long)k2 * 96 + n2]);
    }
}

// ---------------- K1/K2: transpose + LN + projection via mma.sync ----------------
#define LTS 129
#define ASTR2 102
#define WSTR 104
#define LA_OFF 49536
#define LN_SMEM 75648
template<int COUT, bool ISQ>
__global__ void __launch_bounds__(256, 3)
lnproj_mma_kernel(const float* __restrict__ in,
                  const float* __restrict__ gamma,
                  const float* __restrict__ beta,
                  const float* __restrict__ bvec) {
    extern __shared__ __align__(16) char smem[];
    float* tile = (float*)smem;
    __nv_bfloat16* sWT = (__nv_bfloat16*)smem;
    __nv_bfloat16* sA  = (__nv_bfloat16*)(smem + LA_OFF);

    int tid = threadIdx.x, wid = tid >> 5, lane = tid & 31;
    int g = lane >> 2, tig = lane & 3;
    long t0 = (long)blockIdx.x * 128;
    int b  = (int)(t0 / SPD);
    int s0 = (int)(t0 % SPD);
    int r0 = wid * 16;
    uint32_t sb = smem_u32(smem);

    float gm0 = gamma[lane], gm1 = gamma[lane + 32], gm2 = gamma[lane + 64];
    float bt0 = beta[lane],  bt1 = beta[lane + 32],  bt2 = beta[lane + 64];

    const float* inb = in + (long)b * 96 * SPD + s0;
    for (int i = tid; i < 96 * 32; i += 256) {
        int c = i >> 5, t4 = (i & 31) << 2;
        float4 v = *(const float4*)(inb + (long)c * SPD + t4);
        float* tp = tile + c * LTS + t4;
        tp[0] = v.x; tp[1] = v.y; tp[2] = v.z; tp[3] = v.w;
    }
    __syncthreads();

    if (ISQ) {
        for (int i = tid; i < 24 * 128; i += 256) {
            int t = i / 24, c4 = (i % 24) << 2;
            float4 v;
            v.x = tile[(c4 + 0) * LTS + t];
            v.y = tile[(c4 + 1) * LTS + t];
            v.z = tile[(c4 + 2) * LTS + t];
            v.w = tile[(c4 + 3) * LTS + t];
            *(float4*)(g_xt + (t0 + t) * 96 + c4) = v;
        }
    }

    #pragma unroll 1
    for (int it = 0; it < 16; it++) {
        int t = r0 + it;
        float v0 = tile[lane * LTS + t];
        float v1 = tile[(lane + 32) * LTS + t];
        float v2 = tile[(lane + 64) * LTS + t];
        float mean = warp_sum(v0 + v1 + v2) * (1.0f / 96.0f);
        float var  = warp_sum(v0 * v0 + v1 * v1 + v2 * v2) * (1.0f / 96.0f) - mean * mean;
        float inv  = rsqrtf(var + 1e-5f);
        sA[t * ASTR2 + lane]      = __float2bfloat16_rn((v0 - mean) * inv * gm0 + bt0);
        sA[t * ASTR2 + lane + 32] = __float2bfloat16_rn((v1 - mean) * inv * gm1 + bt1);
        sA[t * ASTR2 + lane + 64] = __float2bfloat16_rn((v2 - mean) * inv * gm2 + bt2);
    }

    long base0, base1;
    {
        long bases[2];
        int rows[2] = { r0 + g, r0 + g + 8 };
        #pragma unroll
        for (int rr = 0; rr < 2; rr++) {
            long t = t0 + rows[rr];
            int s = (int)(t % SPD);
            int d = s / (HH * WW_), h = (s / WW_) % HH, w = s % WW_;
            int wi = ((b * NWD + d / WIN_D) * NWH + h / WIN_H) * NWW + w / WIN_W;
            int n  = (d % WIN_D) * 30 + (h % WIN_H) * 5 + (w % WIN_W);
            bases[rr] = ((long)wi * NT + n) * 96;
        }
        base0 = bases[0]; base1 = bases[1];
    }

    const int NHALF = COUT / 96;
    #pragma unroll
    for (int half = 0; half < NHALF; half++) {
        __syncthreads();
        const __nv_bfloat16* wsrc = ISQ ? g_wqT : (half == 0 ? g_wkT : g_wvT);
        for (int i = tid; i < 96 * 12; i += 256) {
            int n = i / 12, c = i % 12;
            cp16(sb + n * (WSTR * 2) + c * 16, (const char*)(wsrc + n * 96) + c * 16);
        }
        CP_COMMIT(); CP_WAIT0();
        __syncthreads();

        float c[12][4];
        #pragma unroll
        for (int nt = 0; nt < 12; nt++) { c[nt][0]=0.f; c[nt][1]=0.f; c[nt][2]=0.f; c[nt][3]=0.f; }
        #pragma unroll
        for (int kk = 0; kk < 6; kk++) {
            int kb = kk * 16 + tig * 2;
            uint32_t a0 = *(const uint32_t*)(sA + (r0 + g)     * ASTR2 + kb);
            uint32_t a1 = *(const uint32_t*)(sA + (r0 + g + 8) * ASTR2 + kb);
            uint32_t a2 = *(const uint32_t*)(sA + (r0 + g)     * ASTR2 + kb + 8);
            uint32_t a3 = *(const uint32_t*)(sA + (r0 + g + 8) * ASTR2 + kb + 8);
            #pragma unroll
            for (int nt = 0; nt < 12; nt++) {
                int n = nt * 8 + g;
                uint32_t b0 = *(const uint32_t*)(sWT + n * WSTR + kb);
                uint32_t b1 = *(const uint32_t*)(sWT + n * WSTR + kb + 8);
                mma16816(c[nt], a0, a1, a2, a3, b0, b1);
            }
        }
        __nv_bfloat16* dst = ISQ ? g_q : (half == 0 ? g_k : g_v);
        #pragma unroll
        for (int nt = 0; nt < 12; nt++) {
            int col = nt * 8 + tig * 2;
            float b0v = __ldg(bvec + half * 96 + col);
            float b1v = __ldg(bvec + half * 96 + col + 1);
            *(uint32_t*)(dst + base0 + col) = pack_bf16(c[nt][0] + b0v, c[nt][1] + b1v);
            *(uint32_t*)(dst + base1 + col) = pack_bf16(c[nt][2] + b0v, c[nt][3] + b1v);
        }
    }
}

// ---------------- K3: attention, 2 CTAs/window, V overlays dead Q+K -> 3 CTAs/SM ----------------
#define AQS 104
#define ASQ_OFF 0          /* Q: 80 x 208  = 16640 */
#define ASK_OFF 16640      /* K: 152 x 208 = 31616; region end 48256 */
#define ASV_OFF 0          /* V: 160 x 208 = 33280, overlays Q+K after GEMM1 */
#define ASW_OFF 48256      /* wproj^T: 96 x 208 = 19968 */
#define ASBP_OFF 68224
#define ATT_SMEM 68608

__global__ void __launch_bounds__(160, 3)
attn_mma_kernel(const float* __restrict__ bproj) {
    extern __shared__ __align__(16) char smem[];
    __nv_bfloat16* sQ  = (__nv_bfloat16*)(smem + ASQ_OFF);
    __nv_bfloat16* sK  = (__nv_bfloat16*)(smem + ASK_OFF);
    __nv_bfloat16* sV  = (__nv_bfloat16*)(smem + ASV_OFF);
    __nv_bfloat16* sWp = (__nv_bfloat16*)(smem + ASW_OFF);
    float* sBp = (float*)(smem + ASBP_OFF);

    int tid = threadIdx.x, wid = tid >> 5, lane = tid & 31;
    int g = lane >> 2, tig = lane & 3;
    int wi   = blockIdx.x >> 1;
    int half = blockIdx.x & 1;
    int r0 = wid * 16;
    int rowoff = half * 80;
    const float scale = 0.102062072615965696f;

    const char* gq = (const char*)(g_q + (long)wi * NT * 96);
    const char* gk = (const char*)(g_k + (long)wi * NT * 96);
    const char* gv = (const char*)(g_v + (long)wi * NT * 96);

    uint32_t sb = smem_u32(smem);
    int qrows = half ? 70 : 80;
    // phase 1: Q + K + wproj
    for (int i = tid; i < qrows * 12; i += 160) {
        int r = i / 12, c = i % 12;
        cp16(sb + ASQ_OFF + r * 208 + c * 16, gq + (rowoff + r) * 192 + c * 16);
    }
    for (int i = tid; i < 150 * 12; i += 160) {
        int r = i / 12, c = i % 12;
        cp16(sb + ASK_OFF + r * 208 + c * 16, gk + r * 192 + c * 16);
    }
    for (int i = tid; i < 96 * 12; i += 160) {
        int n = i / 12, c = i % 12;
        cp16(sb + ASW_OFF + n * 208 + c * 16, (const char*)(g_wpT + n * 96) + c * 16);
    }
    if (tid < 96) sBp[tid] = bproj[tid];
    {
        uint32_t* zk = (uint32_t*)(sK + 150 * AQS);
        for (int i = tid; i < 104; i += 160) zk[i] = 0u;
        if (half) {
            uint32_t* zq = (uint32_t*)(sQ + 70 * AQS);
            for (int i = tid; i < 520; i += 160) zq[i] = 0u;
        }
    }
    CP_COMMIT(); CP_WAIT0();
    __syncthreads();

    // ---- GEMM1: S stripe (16 x 152) ----
    float cs[19][4];
    #pragma unroll
    for (int nt = 0; nt < 19; nt++) { cs[nt][0]=0.f; cs[nt][1]=0.f; cs[nt][2]=0.f; cs[nt][3]=0.f; }
    #pragma unroll
    for (int kk = 0; kk < 6; kk++) {
        int kb = kk * 16 + tig * 2;
        uint32_t a0 = *(const uint32_t*)(sQ + (r0 + g)     * AQS + kb);
        uint32_t a1 = *(const uint32_t*)(sQ + (r0 + g + 8) * AQS + kb);
        uint32_t a2 = *(const uint32_t*)(sQ + (r0 + g)     * AQS + kb + 8);
        uint32_t a3 = *(const uint32_t*)(sQ + (r0 + g + 8) * AQS + kb + 8);
        #pragma unroll
        for (int nt = 0; nt < 19; nt++) {
            int m = nt * 8 + g;
            uint32_t b0 = *(const uint32_t*)(sK + m * AQS + kb);
            uint32_t b1 = *(const uint32_t*)(sK + m * AQS + kb + 8);
            mma16816(cs[nt], a0, a1, a2, a3, b0, b1);
        }
    }

    // ---- softmax (registers only) ----
    int n0r = rowoff + r0 + g, n1r = rowoff + r0 + g + 8;
    float mx0 = -1e30f, mx1 = -1e30f;
    #pragma unroll
    for (int nt = 0; nt < 19; nt++) {
        int m = nt * 8 + tig * 2;
        if (m < NT) {
            if (n0r < NT) {
                float2 bv = *(const float2*)(g_bias + n0r * NT + m);
                cs[nt][0] = cs[nt][0] * scale + bv.x;
                cs[nt][1] = cs[nt][1] * scale + bv.y;
            } else { cs[nt][0] = 0.f; cs[nt][1] = 0.f; }
            if (n1r < NT) {
                float2 bv = *(const float2*)(g_bias + n1r * NT + m);
                cs[nt][2] = cs[nt][2] * scale + bv.x;
                cs[nt][3] = cs[nt][3] * scale + bv.y;
            } else { cs[nt][2] = 0.f; cs[nt][3] = 0.f; }
            mx0 = fmaxf(mx0, fmaxf(cs[nt][0], cs[nt][1]));
            mx1 = fmaxf(mx1, fmaxf(cs[nt][2], cs[nt][3]));
        } else {
            cs[nt][0] = -1e30f; cs[nt][1] = -1e30f;
            cs[nt][2] = -1e30f; cs[nt][3] = -1e30f;
        }
    }
    mx0 = fmaxf(mx0, __shfl_xor_sync(0xffffffffu, mx0, 1));
    mx0 = fmaxf(mx0, __shfl_xor_sync(0xffffffffu, mx0, 2));
    mx1 = fmaxf(mx1, __shfl_xor_sync(0xffffffffu, mx1, 1));
    mx1 = fmaxf(mx1, __shfl_xor_sync(0xffffffffu, mx1, 2));
    float s0 = 0.f, s1 = 0.f;
    #pragma unroll
    for (int nt = 0; nt < 19; nt++) {
        cs[nt][0] = __expf(cs[nt][0] - mx0);
        cs[nt][1] = __expf(cs[nt][1] - mx0);
        cs[nt][2] = __expf(cs[nt][2] - mx1);
        cs[nt][3] = __expf(cs[nt][3] - mx1);
        s0 += cs[nt][0] + cs[nt][1];
        s1 += cs[nt][2] + cs[nt][3];
    }
    s0 += __shfl_xor_sync(0xffffffffu, s0, 1);
    s0 += __shfl_xor_sync(0xffffffffu, s0, 2);
    s1 += __shfl_xor_sync(0xffffffffu, s1, 1);
    s1 += __shfl_xor_sync(0xffffffffu, s1, 2);
    float inv0 = 1.0f / s0, inv1 = 1.0f / s1;

    uint32_t pa[10][4];
    #pragma unroll
    for (int kt = 0; kt < 10; kt++) {
        int e = 2 * kt, o = 2 * kt + 1;
        pa[kt][0] = pack_bf16(cs[e][0] * inv0, cs[e][1] * inv0);
        pa[kt][1] = pack_bf16(cs[e][2] * inv1, cs[e][3] * inv1);
        if (o < 19) {
            pa[kt][2] = pack_bf16(cs[o][0] * inv0, cs[o][1] * inv0);
            pa[kt][3] = pack_bf16(cs[o][2] * inv1, cs[o][3] * inv1);
        } else { pa[kt][2] = 0u; pa[kt][3] = 0u; }
    }

    // ---- phase 2: all warps done with Q/K -> stage V into the dead region ----
    __syncthreads();
    for (int i = tid; i < 150 * 12; i += 160) {
        int r = i / 12, c = i % 12;
        cp16(sb + ASV_OFF + r * 208 + c * 16, gv + r * 192 + c * 16);
    }
    {
        uint32_t* zv = (uint32_t*)(sV + 150 * AQS);
        for (int i = tid; i < 520; i += 160) zv[i] = 0u;
    }
    CP_COMMIT(); CP_WAIT0();
    __syncthreads();

    // ---- GEMM2: O = P @ V ----
    float co[12][4];
    #pragma unroll
    for (int nt = 0; nt < 12; nt++) { co[nt][0]=0.f; co[nt][1]=0.f; co[nt][2]=0.f; co[nt][3]=0.f; }
    #pragma unroll
    for (int kt = 0; kt < 10; kt++) {
        int kb = kt * 16 + tig * 2;
        const uint16_t* v0p = (const uint16_t*)(sV + (kb + 0) * AQS);
        const uint16_t* v1p = (const uint16_t*)(sV + (kb + 1) * AQS);
        const uint16_t* v8p = (const uint16_t*)(sV + (kb + 8) * AQS);
        const uint16_t* v9p = (const uint16_t*)(sV + (kb + 9) * AQS);
        #pragma unroll
        for (int nt = 0; nt < 12; nt++) {
            int n = nt * 8 + g;
            uint32_t b0 = (uint32_t)v0p[n] | ((uint32_t)v1p[n] << 16);
            uint32_t b1 = (uint32_t)v8p[n] | ((uint32_t)v9p[n] << 16);
            mma16816(co[nt], pa[kt][0], pa[kt][1], pa[kt][2], pa[kt][3], b0, b1);
        }
    }

    uint32_t oa[6][4];
    #pragma unroll
    for (int kt = 0; kt < 6; kt++) {
        oa[kt][0] = pack_bf16(co[2*kt][0],   co[2*kt][1]);
        oa[kt][1] = pack_bf16(co[2*kt][2],   co[2*kt][3]);
        oa[kt][2] = pack_bf16(co[2*kt+1][0], co[2*kt+1][1]);
        oa[kt][3] = pack_bf16(co[2*kt+1][2], co[2*kt+1][3]);
    }
    float c2r[12][4];
    #pragma unroll
    for (int nt = 0; nt < 12; nt++) { c2r[nt][0]=0.f; c2r[nt][1]=0.f; c2r[nt][2]=0.f; c2r[nt][3]=0.f; }
    #pragma unroll
    for (int kt = 0; kt < 6; kt++) {
        int kb = kt * 16 + tig * 2;
        #pragma unroll
        for (int nt = 0; nt < 12; nt++) {
            int cp = nt * 8 + g;
            uint32_t b0 = *(const uint32_t*)(sWp + cp * AQS + kb);
            uint32_t b1 = *(const uint32_t*)(sWp + cp * AQS + kb + 8);
            mma16816(c2r[nt], oa[kt][0], oa[kt][1], oa[kt][2], oa[kt][3], b0, b1);
        }
    }

    int iww = wi & 7, iwh = (wi >> 3) & 7, iwd = (wi >> 6) & 7, b = wi >> 9;
    long t0r = -1, t1r = -1;
    if (n0r < NT) {
        int zd = n0r / 30, zh = (n0r / 5) % 6, zw = n0r % 5;
        int d = iwd * WIN_D + zd, h = iwh * WIN_H + zh, w = iww * WIN_W + zw;
        t0r = (long)b * SPD + ((long)d * HH + h) * WW_ + w;
    }
    if (n1r < NT) {
        int zd = n1r / 30, zh = (n1r / 5) % 6, zw = n1r % 5;
        int d = iwd * WIN_D + zd, h = iwh * WIN_H + zh, w = iww * WIN_W + zw;
        t1r = (long)b * SPD + ((long)d * HH + h) * WW_ + w;
    }
    #pragma unroll
    for (int nt = 0; nt < 12; nt++) {
        int cp = nt * 8 + tig * 2;
        float b0v = sBp[cp], b1v = sBp[cp + 1];
        if (t0r >= 0) {
            float2 x = *(const float2*)(g_xt + t0r * 96 + cp);
            float2 o = make_float2(x.x + c2r[nt][0] + b0v, x.y + c2r[nt][1] + b1v);
            *(float2*)(g_x2 + t0r * 96 + cp) = o;
        }
        if (t1r >= 0) {
            float2 x = *(const float2*)(g_xt + t1r * 96 + cp);
            float2 o = make_float2(x.x + c2r[nt][2] + b0v, x.y + c2r[nt][3] + b1v);
            *(float2*)(g_x2 + t1r * 96 + cp) = o;
        }
    }
}

// ---------------- K4: fused LN2 + MLP via mma.sync (round-15 version, reverted) ----------------
#define ASTR 104
#define W1S  104
#define W2S  136
#define MA_OFF    0
#define MW1_OFF   26624
#define MW2_OFF   53248
#define MB1F_OFF  79360
#define MB2F_OFF  80896
#define MLG_OFF   81280
#define MLB_OFF   81664
#define MLP_SMEM  82048

__global__ void __launch_bounds__(256, 2)
mlp_mma_kernel(const float* __restrict__ g2, const float* __restrict__ b2ln,
               const float* __restrict__ b1, const float* __restrict__ b2) {
    extern __shared__ __align__(16) char smem[];
    __nv_bfloat16* sA   = (__nv_bfloat16*)(smem + MA_OFF);
    __nv_bfloat16* sW1T = (__nv_bfloat16*)(smem + MW1_OFF);
    __nv_bfloat16* sW2T = (__nv_bfloat16*)(smem + MW2_OFF);
    float* sb1f = (float*)(smem + MB1F_OFF);
    float* sb2f = (float*)(smem + MB2F_OFF);
    float* slg  = (float*)(smem + MLG_OFF);
    float* slb  = (float*)(smem + MLB_OFF);

    int tid = threadIdx.x, wid = tid >> 5, lane = tid & 31;
    int g = lane >> 2, tig = lane & 3;
    long t0 = (long)blockIdx.x * 128;
    int r0 = wid * 16;
    uint32_t sb = smem_u32(smem);

    for (int i = tid; i < HID; i += 256) sb1f[i] = b1[i];
    if (tid < 96) { sb2f[tid] = b2[tid]; slg[tid] = g2[tid]; slb[tid] = b2ln[tid]; }
    __syncthreads();

    #pragma unroll 1
    for (int it = 0; it < 16; it++) {
        int r = r0 + it;
        const float* xr = g_x2 + (t0 + r) * 96;
        float v0 = xr[lane], v1 = xr[lane + 32], v2 = xr[lane + 64];
        float mean = warp_sum(v0 + v1 + v2) * (1.0f / 96.0f);
        float var  = warp_sum(v0 * v0 + v1 * v1 + v2 * v2) * (1.0f / 96.0f) - mean * mean;
        float inv  = rsqrtf(var + 1e-5f);
        sA[r * ASTR + lane]      = __float2bfloat16_rn((v0 - mean) * inv * slg[lane]      + slb[lane]);
        sA[r * ASTR + lane + 32] = __float2bfloat16_rn((v1 - mean) * inv * slg[lane + 32] + slb[lane + 32]);
        sA[r * ASTR + lane + 64] = __float2bfloat16_rn((v2 - mean) * inv * slg[lane + 64] + slb[lane + 64]);
    }

    float c2[12][4];
    #pragma unroll
    for (int nt = 0; nt < 12; nt++) { c2[nt][0]=0.f; c2[nt][1]=0.f; c2[nt][2]=0.f; c2[nt][3]=0.f; }

    uint32_t h[16][2];

    for (int j = 0; j < 3; j++) {
        __syncthreads();
        for (int i = tid; i < 128 * 12; i += 256) {
            int n = i / 12, c = i % 12;
            cp16(sb + MW1_OFF + n * 208 + c * 16,
                 (const char*)(g_w1T + (long)(j * 128 + n) * 96) + c * 16);
        }
        for (int i = tid; i < 96 * 16; i += 256) {
            int n = i / 16, c = i % 16;
            cp16(sb + MW2_OFF + n * 272 + c * 16,
                 (const char*)(g_w2T + (long)n * HID + j * 128) + c * 16);
        }
        CP_COMMIT(); CP_WAIT0();
        __syncthreads();

        #pragma unroll
        for (int half = 0; half < 2; half++) {
            float c1[8][4];
            #pragma unroll
            for (int nt = 0; nt < 8; nt++) { c1[nt][0]=0.f; c1[nt][1]=0.f; c1[nt][2]=0.f; c1[nt][3]=0.f; }
            #pragma unroll
            for (int kk = 0; kk < 6; kk++) {
                int kb = kk * 16 + tig * 2;
                uint32_t a0 = *(const uint32_t*)(sA + (r0 + g) * ASTR + kb);
                uint32_t a1 = *(const uint32_t*)(sA + (r0 + g + 8) * ASTR + kb);
                uint32_t a2 = *(const uint32_t*)(sA + (r0 + g) * ASTR + kb + 8);
                uint32_t a3 = *(const uint32_t*)(sA + (r0 + g + 8) * ASTR + kb + 8);
                #pragma unroll
                for (int nt = 0; nt < 8; nt++) {
                    int n = (half * 8 + nt) * 8 + g;
                    uint32_t b0 = *(const uint32_t*)(sW1T + n * W1S + kb);
                    uint32_t b1v = *(const uint32_t*)(sW1T + n * W1S + kb + 8);
                    mma16816(c1[nt], a0, a1, a2, a3, b0, b1v);
                }
            }
            #pragma unroll
            for (int nt = 0; nt < 8; nt++) {
                int nn = (half * 8 + nt) * 8 + tig * 2;
                float bb0 = sb1f[j * 128 + nn], bb1 = sb1f[j * 128 + nn + 1];
                h[half * 8 + nt][0] = pack_bf16(gelu_fast(c1[nt][0] + bb0), gelu_fast(c1[nt][1] + bb1));
                h[half * 8 + nt][1] = pack_bf16(gelu_fast(c1[nt][2] + bb0), gelu_fast(c1[nt][3] + bb1));
            }
        }

        #pragma unroll
        for (int kk = 0; kk < 8; kk++) {
            uint32_t a0 = h[2 * kk][0], a1 = h[2 * kk][1];
            uint32_t a2 = h[2 * kk + 1][0], a3 = h[2 * kk + 1][1];
            int kb = kk * 16 + tig * 2;
            #pragma unroll
            for (int nt = 0; nt < 12; nt++) {
                int n = nt * 8 + g;
                uint32_t b0 = *(const uint32_t*)(sW2T + n * W2S + kb);
                uint32_t b1v = *(const uint32_t*)(sW2T + n * W2S + kb + 8);
                mma16816(c2[nt], a0, a1, a2, a3, b0, b1v);
            }
        }
    }

    #pragma unroll
    for (int nt = 0; nt < 12; nt++) {
        int n = nt * 8 + tig * 2;
        long ra = t0 + r0 + g;
        float bb0 = sb2f[n], bb1 = sb2f[n + 1];
        float2 x0 = *(const float2*)(g_x2 + ra * 96 + n);
        float2 x1 = *(const float2*)(g_x2 + (ra + 8) * 96 + n);
        float2 o0 = make_float2(x0.x + c2[nt][0] + bb0, x0.y + c2[nt][1] + bb1);
        float2 o1 = make_float2(x1.x + c2[nt][2] + bb0, x1.y + c2[nt][3] + bb1);
        *(float2*)(g_x3 + ra * 96 + n) = o0;
        *(float2*)(g_x3 + (ra + 8) * 96 + n) = o1;
    }
}

// ---------------- K6: conv3d 3x3x3, 96 -> 3 — row-tiled, 2 w-voxels/thread ----------------
__global__ void __launch_bounds__(160, 4)
conv_kernel(const float* __restrict__ cw, const float* __restrict__ cbias,
            float* __restrict__ out) {
    __shared__ __align__(16) float sWc[27 * 3 * 96];
    __shared__ __align__(16) float sRow[42 * 100];
    __shared__ float sCB[3];
    int tid = threadIdx.x;
    for (int i = tid; i < 27 * 3 * 96; i += 160) {
        int k = i / 288, r = i % 288, o = r / 96, c = r % 96;
        sWc[i] = cw[((long)o * 96 + c) * 27 + k];
    }
    if (tid < 3) sCB[tid] = cbias[tid];

    int bid = blockIdx.x;
    int hg = bid % 6, d = (bid / 6) % DD, b = bid / (6 * DD);
    int h0 = hg * 8;
    int h_local = tid / 20, wl = tid % 20;
    int h = h0 + h_local;

    float acc[2][3];
    #pragma unroll
    for (int v = 0; v < 2; v++) { acc[v][0] = 0.f; acc[v][1] = 0.f; acc[v][2] = 0.f; }

    for (int d2 = d - 1; d2 <= d + 1; d2++) {
        if ((unsigned)d2 >= DD) continue;
        int kd = d2 - d;
        for (int h2 = h0 - 1; h2 <= h0 + 8; h2++) {
            if ((unsigned)h2 >= HH) continue;
            __syncthreads();
            const float4* src = (const float4*)(g_x3 +
                ((long)b * SPD + (long)d2 * HH * WW_ + (long)h2 * WW_) * 96);
            for (int i = tid; i < 960; i += 160) {
                int w2 = i / 24, c4 = i % 24;
                *(float4*)(sRow + (w2 + 1) * 100 + c4 * 4) = src[i];
            }
            if (tid < 48) {
                int v = tid / 24, c4 = tid % 24;
                int w2p = v ? 41 : 0;
                *(float4*)(sRow + w2p * 100 + c4 * 4) = make_float4(0.f, 0.f, 0.f, 0.f);
            }
            __syncthreads();
            int kh = h2 - h;
            if (kh < -1 || kh > 1) continue;
            #pragma unroll
            for (int kw = -1; kw <= 1; kw++) {
                int k = (kd + 1) * 9 + (kh + 1) * 3 + (kw + 1);
                const float4* wk  = (const float4*)(sWc + k * 288);
                const float4* xr0 = (const float4*)(sRow + (wl + kw + 1) * 100);
                const float4* xr1 = (const float4*)(sRow + (wl + 20 + kw + 1) * 100);
                float a00 = 0.f, a01 = 0.f, a02 = 0.f;
                float a10 = 0.f, a11 = 0.f, a12 = 0.f;
                #pragma unroll 8
                for (int c4 = 0; c4 < 24; c4++) {
                    float4 x0 = xr0[c4];
                    float4 x1 = xr1[c4];
                    float4 w0 = wk[c4];
                    float4 w1 = wk[24 + c4];
                    float4 w2v = wk[48 + c4];
                    a00 += x0.x * w0.x + x0.y * w0.y + x0.z * w0.z + x0.w * w0.w;
                    a01 += x0.x * w1.x + x0.y * w1.y + x0.z * w1.z + x0.w * w1.w;
                    a02 += x0.x * w2v.x + x0.y * w2v.y + x0.z * w2v.z + x0.w * w2v.w;
                    a10 += x1.x * w0.x + x1.y * w0.y + x1.z * w0.z + x1.w * w0.w;
                    a11 += x1.x * w1.x + x1.y * w1.y + x1.z * w1.z + x1.w * w1.w;
                    a12 += x1.x * w2v.x + x1.y * w2v.y + x1.z * w2v.z + x1.w * w2v.w;
                }
                acc[0][0] += a00; acc[0][1] += a01; acc[0][2] += a02;
                acc[1][0] += a10; acc[1][1] += a11; acc[1][2] += a12;
            }
        }
    }
    #pragma unroll
    for (int v = 0; v < 2; v++) {
        long sp = (long)d * HH * WW_ + (long)h * WW_ + (wl + 20 * v);
        #pragma unroll
        for (int o = 0; o < 3; o++)
            out[((long)b * 3 + o) * SPD + sp] = acc[v][o] + sCB[o];
    }
}

// ---------------- launch (stream fork/join for the independent front) ----------------
extern "C" void kernel_launch(void* const* d_in, const int* in_sizes, int n_in,
                              void* d_out, int out_size) {
    const float* I_m    = (const float*)d_in[0];
    const float* I_f    = (const float*)d_in[1];
    const float* ln1q_g = (const float*)d_in[2];
    const float* ln1q_b = (const float*)d_in[3];
    const float* ln1kv_g= (const float*)d_in[4];
    const float* ln1kv_b= (const float*)d_in[5];
    const float* wq     = (const float*)d_in[6];
    const float* bq     = (const float*)d_in[7];
    const float* wkv    = (const float*)d_in[8];
    const float* bkv    = (const float*)d_in[9];
    const float* wproj  = (const float*)d_in[10];
    const float* bproj  = (const float*)d_in[11];
    const float* relb   = (const float*)d_in[12];
    const float* ln2_g  = (const float*)d_in[13];
    const float* ln2_b  = (const float*)d_in[14];
    const float* w1     = (const float*)d_in[15];
    const float* b1     = (const float*)d_in[16];
    const float* w2     = (const float*)d_in[17];
    const float* b2     = (const float*)d_in[18];
    const float* cw     = (const float*)d_in[19];
    const float* cb     = (const float*)d_in[20];
    float* out = (float*)d_out;

    static cudaStream_t s1, s2, s3;
    static cudaEvent_t efork, ej1, ej2, ej3;
    static bool inited = false;
    if (!inited) {
        cudaStreamCreateWithFlags(&s1, cudaStreamNonBlocking);
        cudaStreamCreateWithFlags(&s2, cudaStreamNonBlocking);
        cudaStreamCreateWithFlags(&s3, cudaStreamNonBlocking);
        cudaEventCreateWithFlags(&efork, cudaEventDisableTiming);
        cudaEventCreateWithFlags(&ej1, cudaEventDisableTiming);
        cudaEventCreateWithFlags(&ej2, cudaEventDisableTiming);
        cudaEventCreateWithFlags(&ej3, cudaEventDisableTiming);
        inited = true;
    }

    cudaFuncSetAttribute(lnproj_mma_kernel<96,  true >, cudaFuncAttributeMaxDynamicSharedMemorySize, LN_SMEM);
    cudaFuncSetAttribute(lnproj_mma_kernel<192, false>, cudaFuncAttributeMaxDynamicSharedMemorySize, LN_SMEM);
    cudaFuncSetAttribute(attn_mma_kernel, cudaFuncAttributeMaxDynamicSharedMemorySize, ATT_SMEM);
    cudaFuncSetAttribute(mlp_mma_kernel, cudaFuncAttributeMaxDynamicSharedMemorySize, MLP_SMEM);

    cudaStream_t s0 = 0;

    cudaEventRecord(efork, s0);
    cudaStreamWaitEvent(s1, efork, 0);
    cudaStreamWaitEvent(s2, efork, 0);
    cudaStreamWaitEvent(s3, efork, 0);

    bias_kernel<<<(NT*NT + 255) / 256, 256, 0, s1>>>(relb);
    prep_w_kernel<<<144, 256, 0, s1>>>(wq, wkv, wproj, w1, w2);
    lnproj_mma_kernel<96,  true ><<<TOT / 128, 256, LN_SMEM, s2>>>(I_m, ln1q_g,  ln1q_b,  bq);
    lnproj_mma_kernel<192, false><<<TOT / 128, 256, LN_SMEM, s3>>>(I_f, ln1kv_g, ln1kv_b, bkv);

    cudaEventRecord(ej1, s1);
    cudaEventRecord(ej2, s2);
    cudaEventRecord(ej3, s3);
    cudaStreamWaitEvent(s0, ej1, 0);
    cudaStreamWaitEvent(s0, ej2, 0);
    cudaStreamWaitEvent(s0, ej3, 0);

    attn_mma_kernel<<<NWIN * 2, 160, ATT_SMEM, s0>>>(bproj);
    mlp_mma_kernel<<<TOT / 128, 256, MLP_SMEM, s0>>>(ln2_g, ln2_b, b1, b2);
    conv_kernel<<<BB * DD * 6, 160, 0, s0>>>(cw, cb, out);
}